// round 7
// baseline (speedup 1.0000x reference)
#include <cuda_runtime.h>

#define N_  128
#define D_  512
#define IC_ 32
#define OC_ 8
#define R_  4

// shared layout (float offsets), 32-n block:
//  s_x : [0, 4224)        x staging [p=128][n=32] pitch 33
//  s_v : [4224, 8448)     v staging
//  w4  : [8448, 10496)    packed weights (w_e,w_o,w2_e,w2_o) per (r,ic,ocpair)
//  P   : [10496, 10760)   8*33 reduction partials
//  sm  : [10760, 10792)   per-group max
//  sis : [10792, 10824)   per-group 1/sum
#define SMEM_FLOATS 10824
#define SMEM_BYTES  (SMEM_FLOATS * 4)

typedef unsigned long long u64;

__device__ __forceinline__ u64 pack2(float lo, float hi) {
    u64 r; asm("mov.b64 %0, {%1, %2};" : "=l"(r) : "f"(lo), "f"(hi)); return r;
}
__device__ __forceinline__ void unpack2(u64 v, float& lo, float& hi) {
    asm("mov.b64 {%0, %1}, %2;" : "=f"(lo), "=f"(hi) : "l"(v));
}
__device__ __forceinline__ u64 ffma2(u64 a, u64 b, u64 c) {
    u64 d; asm("fma.rn.f32x2 %0, %1, %2, %3;" : "=l"(d) : "l"(a), "l"(b), "l"(c)); return d;
}
__device__ __forceinline__ u64 fadd2(u64 a, u64 b) {
    u64 d; asm("add.rn.f32x2 %0, %1, %2;" : "=l"(d) : "l"(a), "l"(b)); return d;
}
__device__ __forceinline__ unsigned smem_u32(const void* p) {
    unsigned r;
    asm("{ .reg .u64 t; cvta.to.shared.u64 t, %1; cvt.u32.u64 %0, t; }" : "=r"(r) : "l"(p));
    return r;
}
__device__ __forceinline__ void cp4(unsigned dst, const float* src) {
    asm volatile("cp.async.ca.shared.global [%0], [%1], 4;" :: "r"(dst), "l"(src));
}

__global__ __launch_bounds__(256, 4) void fused_kernel(const float* __restrict__ x,
                                                       const float* __restrict__ v,
                                                       const float* __restrict__ weights,
                                                       float* __restrict__ out) {
    extern __shared__ float smem[];
    float* s_x   = smem;
    float* s_v   = smem + 4224;
    float* s_w4f = smem + 8448;
    float* s_P   = smem + 10496;
    float* s_m   = smem + 10760;
    float* s_is  = smem + 10792;

    const int t  = threadIdx.x;
    const int d  = blockIdx.y;
    const int n0 = blockIdx.x << 5;            // 0,32,64,96

    // ---- weight LDG first (in flight during cp.async burst) ----
    const float* wd = weights + d * (IC_ * OC_ * R_);
    float raw[4];
    #pragma unroll
    for (int k = 0; k < 4; k++) raw[k] = wd[t + 256 * k];

    // ---- fire-and-forget async staging of x/v, [p][n] pitch 33 ----
    {
        const int p  = t & 127;
        const int jh = t >> 7;                  // n-range jh*16 .. +16
        const size_t gbase = (size_t)(n0 + jh * 16) * (D_ * 128) + (size_t)d * 128 + p;
        const float* xg = x + gbase;
        const float* vg = v + gbase;
        const unsigned sx = smem_u32(s_x) + (p * 33 + jh * 16) * 4;
        const unsigned sv = smem_u32(s_v) + (p * 33 + jh * 16) * 4;
        #pragma unroll 8
        for (int j = 0; j < 16; j++) {
            cp4(sx + j * 4, xg + (size_t)j * (D_ * 128));
            cp4(sv + j * 4, vg + (size_t)j * (D_ * 128));
        }
        asm volatile("cp.async.commit_group;");
    }

    // ---- parallel softmax over IC per group g = oc*4+r (overlaps DRAM) ----
    const int w  = t >> 5;
    const int ln = t & 31;
    s_P[w * 33 + ln] = fmaxf(fmaxf(raw[0], raw[1]), fmaxf(raw[2], raw[3]));
    __syncthreads();
    if (t < 32) {
        float m = s_P[t];
        #pragma unroll
        for (int q = 1; q < 8; q++) m = fmaxf(m, s_P[q * 33 + t]);
        s_m[t] = m;
    }
    __syncthreads();
    float e4[4];
    {
        const float mg = s_m[ln];
        float s = 0.0f;
        #pragma unroll
        for (int k = 0; k < 4; k++) { e4[k] = __expf(raw[k] - mg); s += e4[k]; }
        s_P[w * 33 + ln] = s;
    }
    __syncthreads();
    if (t < 32) {
        float s = s_P[t];
        #pragma unroll
        for (int q = 1; q < 8; q++) s += s_P[q * 33 + t];
        s_is[t] = 1.0f / s;
    }
    __syncthreads();
    {
        const float isr = s_is[ln];
        const int oc = ln >> 2, rr = ln & 3;
        #pragma unroll
        for (int k = 0; k < 4; k++) {
            const int ic = w + 8 * k;
            const float wv = e4[k] * isr;
            const int base = ((rr * 32 + ic) * 4 + (oc >> 1)) * 4 + (oc & 1);
            s_w4f[base]     = wv;
            s_w4f[base + 2] = wv * wv;
        }
    }
    asm volatile("cp.async.wait_group 0;");
    __syncthreads();

    // ---- main accumulation: warp w = (r = w>>1, q = w&1), lane = n; ic split by q ----
    const int r = w >> 1;
    const int q = w & 1;
    const int n = ln;

    u64 a1[4], aR[4], aL[4];
    #pragma unroll
    for (int o = 0; o < 4; o++) { a1[o] = 0ull; aR[o] = 0ull; aL[o] = 0ull; }

    const float4* wb = (const float4*)s_w4f + (size_t)r * 128;
    const float*  xr = s_x + n;
    const float*  vr = s_v + n;

    #pragma unroll 8
    for (int ii = 0; ii < 16; ii++) {
        const int ic  = q * 16 + ii;
        const int off = (ic * 4 + r) * 33;
        const float xv = xr[off];
        const float vv = vr[off];
        const float e = __expf(xv);
        const float f = __expf(vv);
        const float qq = e * e;
        const u64 bS = pack2(e, e);
        const u64 bR = pack2(qq, qq);
        const u64 bL = pack2(f, f);
        const float4* wi = wb + ic * 4;
        #pragma unroll
        for (int o = 0; o < 4; o++) {
            const float4 w4 = wi[o];              // broadcast LDS.128
            a1[o] = ffma2(pack2(w4.x, w4.y), bS, a1[o]);
            aR[o] = ffma2(pack2(w4.z, w4.w), bR, aR[o]);
            aL[o] = ffma2(pack2(w4.z, w4.w), bL, aL[o]);
        }
    }
    __syncthreads();   // done reading s_x/s_v

    // ---- cross-q reduction via smem (s_x reused; [item][13] u64, pitch 26 floats) ----
    u64* s_red = (u64*)s_x;
    const int item = r * 32 + n;
    if (q == 1) {
        u64* dst = s_red + item * 13;
        #pragma unroll
        for (int o = 0; o < 4; o++) {
            dst[o]     = a1[o];
            dst[4 + o] = aR[o];
            dst[8 + o] = aL[o];
        }
    }
    __syncthreads();
    if (q == 0) {
        const u64* src = s_red + item * 13;
        #pragma unroll
        for (int o = 0; o < 4; o++) {
            a1[o] = fadd2(a1[o], src[o]);
            aR[o] = fadd2(aR[o], src[4 + o]);
            aL[o] = fadd2(aL[o], src[8 + o]);
        }
    }

    // ---- logs -> [c][n] staging in s_v region (pitch 33) ----
    float* st_p = s_v;            // 32*33 = 1056
    float* st_v = s_v + 1056;     // 32*33
    if (q == 0) {
        #pragma unroll
        for (int o = 0; o < 4; o++) {
            float s1a, s1b, sra, srb, sla, slb;
            unpack2(a1[o], s1a, s1b);
            unpack2(aR[o], sra, srb);
            unpack2(aL[o], sla, slb);
            const int c0 = (2 * o) * 4 + r;
            const int c1 = (2 * o + 1) * 4 + r;
            st_p[c0 * 33 + n] = __logf(s1a);
            st_p[c1 * 33 + n] = __logf(s1b);
            st_v[c0 * 33 + n] = __logf(sra + sla);
            st_v[c1 * 33 + n] = __logf(srb + slb);
        }
    }
    __syncthreads();

    // ---- STG.128 coalesced stores ----
    {
        float* op = out + (size_t)n0 * (D_ * 32) + (size_t)d * 32;
        float* ov = op + (size_t)N_ * D_ * 32;
        #pragma unroll
        for (int m = 0; m < 2; m++) {
            const int i   = t + 256 * m;         // 0..511
            const int arr = i >> 8;              // 0: lp, 1: lv
            const int nl  = (i >> 3) & 31;
            const int qd  = i & 7;
            const float* src = arr ? st_v : st_p;
            float4 a;
            a.x = src[(4 * qd + 0) * 33 + nl];
            a.y = src[(4 * qd + 1) * 33 + nl];
            a.z = src[(4 * qd + 2) * 33 + nl];
            a.w = src[(4 * qd + 3) * 33 + nl];
            float* dst = arr ? ov : op;
            *(float4*)(dst + (size_t)nl * (D_ * 32) + 4 * qd) = a;
        }
    }
}

extern "C" void kernel_launch(void* const* d_in, const int* in_sizes, int n_in,
                              void* d_out, int out_size) {
    const float* x       = (const float*)d_in[0];
    const float* vars    = (const float*)d_in[1];
    const float* weights = (const float*)d_in[2];
    float* out = (float*)d_out;

    cudaFuncSetAttribute(fused_kernel, cudaFuncAttributeMaxDynamicSharedMemorySize, SMEM_BYTES);
    dim3 grid(4, 512);
    fused_kernel<<<grid, 256, SMEM_BYTES>>>(x, vars, weights, out);
}